// round 13
// baseline (speedup 1.0000x reference)
#include <cuda_runtime.h>
#include <cuda_bf16.h>
#include <mma.h>
#include <math.h>
#include <stdint.h>

using namespace nvcuda;

#define N_NODES 50000
#define N_EDGES 800000
#define IN_DIM  128
#define FEAT    64
#define NXW 3200000                 // N_NODES*64 float2-units of x
#define WELEMS 45056                // pre_w(8192) + 3x w(12288)
#define COUNT_BLOCKS 3125
#define PREP_BLOCKS ((NXW + WELEMS + 255) / 256)

// ---------------- scratch (static device globals; no allocation) ----------------
__device__ float    g_H0[N_NODES * FEAT];
__device__ float    g_H1[N_NODES * FEAT];
__device__ unsigned g_Ahi[N_NODES * 96];     // split-bf16 A, packed bf16x2
__device__ unsigned g_Alo[N_NODES * 96];
__device__ __nv_bfloat16 g_Bhi[WELEMS];      // weights row-major [K,64], split-bf16
__device__ __nv_bfloat16 g_Blo[WELEMS];
__device__ int      g_cnt[N_NODES];          // zero-init at load; re-zeroed in scan
__device__ int      g_off[N_NODES + 1];
__device__ int      g_pos[N_NODES];
__device__ float4   g_ecsr[N_EDGES];         // packed (src_bits, ea0, ea1, ea2) in CSR order

__device__ __forceinline__ float* sel_buf(int s) { return (s == 0) ? g_H0 : g_H1; }

__device__ __forceinline__ unsigned pack_bf2(__nv_bfloat16 a, __nv_bfloat16 b) {
    return ((unsigned)__bfloat16_as_ushort(b) << 16) | (unsigned)__bfloat16_as_ushort(a);
}
__device__ __forceinline__ void split2(float x, float y, unsigned& hi, unsigned& lo) {
    __nv_bfloat16 hx = __float2bfloat16(x), hy = __float2bfloat16(y);
    __nv_bfloat16 lx = __float2bfloat16(x - __bfloat162float(hx));
    __nv_bfloat16 ly = __float2bfloat16(y - __bfloat162float(hy));
    hi = pack_bf2(hx, hy);
    lo = pack_bf2(lx, ly);
}

// ---------------- K1: count in-degrees | prep (x + weights -> split bf16) ----------
__global__ void __launch_bounds__(256)
k_count_prep(const int* __restrict__ ei, const float* __restrict__ x,
             const float* __restrict__ pre_w, const float* __restrict__ w1,
             const float* __restrict__ w2, const float* __restrict__ w3)
{
    int b = blockIdx.x;
    if (b < COUNT_BLOCKS) {
        int e = b * 256 + threadIdx.x;
        if (e < N_EDGES) atomicAdd(&g_cnt[ei[N_EDGES + e]], 1);
    } else {
        int idx = (b - COUNT_BLOCKS) * 256 + threadIdx.x;
        if (idx < NXW) {
            float2 v = ((const float2*)x)[idx];
            unsigned hi, lo;
            split2(v.x, v.y, hi, lo);
            g_Ahi[idx] = hi;
            g_Alo[idx] = lo;
        } else {
            int j = idx - NXW;
            if (j < WELEMS) {
                const float* W; int off;
                if (j < 8192)       { W = pre_w; off = 0;     }
                else if (j < 20480) { W = w1;    off = 8192;  j -= 8192;  }
                else if (j < 32768) { W = w2;    off = 20480; j -= 20480; }
                else                { W = w3;    off = 32768; j -= 32768; }
                float wv = W[j];
                __nv_bfloat16 hi = __float2bfloat16(wv);
                g_Bhi[off + j] = hi;
                g_Blo[off + j] = __float2bfloat16(wv - __bfloat162float(hi));
            }
        }
    }
}

// ---------------- fill: packed CSR records ----------------
__global__ void fill_csr_kernel(const int* __restrict__ ei, const float* __restrict__ ea) {
    int e = blockIdx.x * blockDim.x + threadIdx.x;
    if (e < N_EDGES) {
        int t  = ei[N_EDGES + e];
        int s  = ei[e];
        float a0 = __ldg(&ea[(size_t)e * 3 + 0]);
        float a1 = __ldg(&ea[(size_t)e * 3 + 1]);
        float a2 = __ldg(&ea[(size_t)e * 3 + 2]);
        int slot = atomicAdd(&g_pos[t], 1);
        g_ecsr[slot] = make_float4(__int_as_float(s), a0, a1, a2);
    }
}

// ---------------- edge aggregation (packed metadata, unroll-4) ----------------
__global__ void __launch_bounds__(256)
agg_kernel(int hsel)
{
    __shared__ float4 sE[8][32];
    int w = threadIdx.x >> 5;
    int node = blockIdx.x * 8 + w;
    if (node >= N_NODES) return;
    int lane = threadIdx.x & 31;
    const float* H = sel_buf(hsel);
    int off = g_off[node];
    int deg = g_off[node + 1] - off;

    float s0x = 0.f, s0y = 0.f, s1x = 0.f, s1y = 0.f, s2x = 0.f, s2y = 0.f;

    for (int base = 0; base < deg; base += 32) {
        if (base + lane < deg) sE[w][lane] = __ldg(&g_ecsr[off + base + lane]);
        __syncwarp();
        int m = min(32, deg - base);
        int k = 0;
        for (; k + 4 <= m; k += 4) {
            float4 e0 = sE[w][k], e1 = sE[w][k + 1], e2 = sE[w][k + 2], e3 = sE[w][k + 3];
            float2 h0 = __ldg(&((const float2*)(H + (size_t)__float_as_int(e0.x) * 64))[lane]);
            float2 h1 = __ldg(&((const float2*)(H + (size_t)__float_as_int(e1.x) * 64))[lane]);
            float2 h2 = __ldg(&((const float2*)(H + (size_t)__float_as_int(e2.x) * 64))[lane]);
            float2 h3 = __ldg(&((const float2*)(H + (size_t)__float_as_int(e3.x) * 64))[lane]);
            s0x += e0.y * h0.x; s0y += e0.y * h0.y;
            s1x += e0.z * h0.x; s1y += e0.z * h0.y;
            s2x += e0.w * h0.x; s2y += e0.w * h0.y;
            s0x += e1.y * h1.x; s0y += e1.y * h1.y;
            s1x += e1.z * h1.x; s1y += e1.z * h1.y;
            s2x += e1.w * h1.x; s2y += e1.w * h1.y;
            s0x += e2.y * h2.x; s0y += e2.y * h2.y;
            s1x += e2.z * h2.x; s1y += e2.z * h2.y;
            s2x += e2.w * h2.x; s2y += e2.w * h2.y;
            s0x += e3.y * h3.x; s0y += e3.y * h3.y;
            s1x += e3.z * h3.x; s1y += e3.z * h3.y;
            s2x += e3.w * h3.x; s2y += e3.w * h3.y;
        }
        for (; k < m; k++) {
            float4 ed = sE[w][k];
            float2 hv = __ldg(&((const float2*)(H + (size_t)__float_as_int(ed.x) * 64))[lane]);
            s0x += ed.y * hv.x; s0y += ed.y * hv.y;
            s1x += ed.z * hv.x; s1y += ed.z * hv.y;
            s2x += ed.w * hv.x; s2y += ed.w * hv.y;
        }
        __syncwarp();
    }

    float inv = 1.0f / fmaxf((float)deg, 1.0f);
    size_t rb = (size_t)node * 96;
    unsigned hi, lo;
    split2(s0x * inv, s0y * inv, hi, lo); g_Ahi[rb + lane]      = hi; g_Alo[rb + lane]      = lo;
    split2(s1x * inv, s1y * inv, hi, lo); g_Ahi[rb + 32 + lane] = hi; g_Alo[rb + 32 + lane] = lo;
    split2(s2x * inv, s2y * inv, hi, lo); g_Ahi[rb + 64 + lane] = hi; g_Alo[rb + 64 + lane] = lo;
}

// ---------------- WMMA bf16 split GEMM body (pipelined), fused epilogue ----------------
#define GA_ST 40
#define GB_ST 72
__device__ __forceinline__ void
gemm_body(int bid, int K, int boff, const float* __restrict__ bias,
          int do_relu, int do_norm, int csel, float* __restrict__ extout,
          unsigned char* smemraw)
{
    __nv_bfloat16* sAh = (__nv_bfloat16*)smemraw;
    __nv_bfloat16* sAl = sAh + 128 * GA_ST;
    __nv_bfloat16* sBh = sAl + 128 * GA_ST;
    __nv_bfloat16* sBl = sBh + 32 * GB_ST;
    float* sOut = (float*)smemraw;

    const int tid = threadIdx.x;
    const int wid = tid >> 5;
    const int lane = tid & 31;
    const int row0cta = bid * 128;
    const int chunks = K >> 5;

    const __nv_bfloat16* Ah = (const __nv_bfloat16*)g_Ahi;
    const __nv_bfloat16* Al = (const __nv_bfloat16*)g_Alo;
    const __nv_bfloat16* Bh = g_Bhi + boff;
    const __nv_bfloat16* Bl = g_Blo + boff;

    const int ar0 = tid >> 2, aq = tid & 3;
    const int ar1 = 64 + ar0;
    const int brow = tid >> 3, bq = tid & 7;
    const int ga0 = row0cta + ar0, ga1 = row0cta + ar1;

    wmma::fragment<wmma::accumulator, 16, 16, 16, float> acc[4];
    #pragma unroll
    for (int j = 0; j < 4; j++) wmma::fill_fragment(acc[j], 0.0f);

    uint4 rah0, rah1, ral0, ral1, rbh, rbl;
    const uint4 z4 = make_uint4(0, 0, 0, 0);

    rah0 = (ga0 < N_NODES) ? ((const uint4*)(Ah + (size_t)ga0 * K))[aq] : z4;
    rah1 = (ga1 < N_NODES) ? ((const uint4*)(Ah + (size_t)ga1 * K))[aq] : z4;
    ral0 = (ga0 < N_NODES) ? ((const uint4*)(Al + (size_t)ga0 * K))[aq] : z4;
    ral1 = (ga1 < N_NODES) ? ((const uint4*)(Al + (size_t)ga1 * K))[aq] : z4;
    rbh  = ((const uint4*)(Bh + (size_t)brow * 64))[bq];
    rbl  = ((const uint4*)(Bl + (size_t)brow * 64))[bq];

    for (int c = 0; c < chunks; c++) {
        __syncthreads();
        ((uint4*)sAh)[ar0 * 5 + aq] = rah0;
        ((uint4*)sAh)[ar1 * 5 + aq] = rah1;
        ((uint4*)sAl)[ar0 * 5 + aq] = ral0;
        ((uint4*)sAl)[ar1 * 5 + aq] = ral1;
        ((uint4*)sBh)[brow * 9 + bq] = rbh;
        ((uint4*)sBl)[brow * 9 + bq] = rbl;
        if (c + 1 < chunks) {
            int k0 = (c + 1) << 5;
            rah0 = (ga0 < N_NODES) ? ((const uint4*)(Ah + (size_t)ga0 * K + k0))[aq] : z4;
            rah1 = (ga1 < N_NODES) ? ((const uint4*)(Ah + (size_t)ga1 * K + k0))[aq] : z4;
            ral0 = (ga0 < N_NODES) ? ((const uint4*)(Al + (size_t)ga0 * K + k0))[aq] : z4;
            ral1 = (ga1 < N_NODES) ? ((const uint4*)(Al + (size_t)ga1 * K + k0))[aq] : z4;
            rbh  = ((const uint4*)(Bh + (size_t)(k0 + brow) * 64))[bq];
            rbl  = ((const uint4*)(Bl + (size_t)(k0 + brow) * 64))[bq];
        }
        __syncthreads();
        #pragma unroll
        for (int ks = 0; ks < 2; ks++) {
            wmma::fragment<wmma::matrix_a, 16, 16, 16, __nv_bfloat16, wmma::row_major> ah, al;
            wmma::load_matrix_sync(ah, sAh + wid * 16 * GA_ST + ks * 16, GA_ST);
            wmma::load_matrix_sync(al, sAl + wid * 16 * GA_ST + ks * 16, GA_ST);
            #pragma unroll
            for (int j = 0; j < 4; j++) {
                wmma::fragment<wmma::matrix_b, 16, 16, 16, __nv_bfloat16, wmma::row_major> bh, bl;
                wmma::load_matrix_sync(bh, sBh + ks * 16 * GB_ST + j * 16, GB_ST);
                wmma::load_matrix_sync(bl, sBl + ks * 16 * GB_ST + j * 16, GB_ST);
                wmma::mma_sync(acc[j], ah, bh, acc[j]);
                wmma::mma_sync(acc[j], al, bh, acc[j]);
                wmma::mma_sync(acc[j], ah, bl, acc[j]);
            }
        }
    }

    __syncthreads();
    #pragma unroll
    for (int j = 0; j < 4; j++)
        wmma::store_matrix_sync(&sOut[wid * 1024 + j * 16], acc[j], 64, wmma::mem_row_major);
    __syncwarp();

    int r = lane & 15, half = lane >> 4;
    int row = row0cta + wid * 16 + r;
    const float* src = &sOut[wid * 1024 + r * 64 + half * 32];
    float v[32];
    float ss = 0.0f;
    #pragma unroll
    for (int j = 0; j < 32; j++) {
        v[j] = src[j] + __ldg(&bias[half * 32 + j]);
        if (do_relu) v[j] = fmaxf(v[j], 0.0f);
        ss += v[j] * v[j];
    }
    if (do_norm) {
        ss += __shfl_xor_sync(0xffffffffu, ss, 16);
        float rr = 1.0f / fmaxf(sqrtf(ss), 1e-12f);
        #pragma unroll
        for (int j = 0; j < 32; j++) v[j] *= rr;
    }
    if (row < N_NODES) {
        float* C = (csel < 0) ? extout : sel_buf(csel);
        float4* po = (float4*)(C + (size_t)row * 64 + half * 32);
        #pragma unroll
        for (int j = 0; j < 8; j++)
            po[j] = make_float4(v[4 * j], v[4 * j + 1], v[4 * j + 2], v[4 * j + 3]);
    }
}

__global__ void __launch_bounds__(256)
gemm_wmma(int K, int boff, const float* __restrict__ bias,
          int do_relu, int do_norm, int csel, float* __restrict__ extout)
{
    __shared__ __align__(16) unsigned char smemraw[33 * 1024];
    gemm_body(blockIdx.x, K, boff, bias, do_relu, do_norm, csel, extout, smemraw);
}

// ---------------- K2: block 0 = CSR scan (+cnt reset) | blocks 1.. = gemm0 ----------
__global__ void __launch_bounds__(256)
k_scan_gemm0(const float* __restrict__ bias)
{
    __shared__ __align__(16) unsigned char smemraw[33 * 1024];
    if (blockIdx.x == 0) {
        int* ssum = (int*)smemraw;
        const int CH = 196;                    // 256*196 = 50176 >= N_NODES
        int t = threadIdx.x;
        int start = t * CH;
        int local = 0;
        for (int i = start; i < start + CH; i++)
            if (i < N_NODES) local += g_cnt[i];
        ssum[t] = local;
        __syncthreads();
        #pragma unroll
        for (int d = 1; d < 256; d <<= 1) {
            int x = (t >= d) ? ssum[t - d] : 0;
            __syncthreads(); ssum[t] += x; __syncthreads();
        }
        int running = ssum[t] - local;         // exclusive prefix
        for (int i = start; i < start + CH; i++) {
            if (i < N_NODES) {
                int c = g_cnt[i];
                g_off[i] = running;
                g_pos[i] = running;
                g_cnt[i] = 0;                  // reset for next replay
                running += c;
            }
        }
        if (t == 0) g_off[N_NODES] = N_EDGES;
    } else {
        gemm_body(blockIdx.x - 1, IN_DIM, 0, bias, 0, 0, 0, nullptr, smemraw);
    }
}

// ---------------- launch (kernel launches ONLY — graph-capture safe) ----------------
extern "C" void kernel_launch(void* const* d_in, const int* in_sizes, int n_in,
                              void* d_out, int out_size)
{
    const float* x     = (const float*)d_in[0];
    const int*   ei    = (const int*)  d_in[1];   // [2, E]
    const float* ea    = (const float*)d_in[2];   // [E, 3]
    const float* pre_w = (const float*)d_in[3];   // [128, 64]
    const float* pre_b = (const float*)d_in[4];   // [64]
    const float* w[3]  = {(const float*)d_in[5], (const float*)d_in[7], (const float*)d_in[9]};
    const float* b[3]  = {(const float*)d_in[6], (const float*)d_in[8], (const float*)d_in[10]};
    float* out = (float*)d_out;

    const int gemm_blocks = (N_NODES + 127) / 128;   // 391

    // K1: in-degree count | all dtype prep (independent halves, one launch)
    k_count_prep<<<COUNT_BLOCKS + PREP_BLOCKS, 256>>>(ei, x, pre_w, w[0], w[1], w[2]);
    // K2: CSR offset scan (block 0) | linear_pre gemm (blocks 1..391)
    k_scan_gemm0<<<gemm_blocks + 1, 256>>>(pre_b);
    // K3: packed CSR fill
    fill_csr_kernel<<<(N_EDGES + 255) / 256, 256>>>(ei, ea);

    int hin = 0, hout = 1;
    for (int l = 0; l < 3; l++) {
        agg_kernel<<<(N_NODES + 7) / 8, 256>>>(hin);      // -> split-bf16 A (K=192)
        int boff = 8192 + l * 12288;
        if (l < 2) {
            gemm_wmma<<<gemm_blocks, 256>>>(192, boff, b[l], 1, 0, hout, nullptr);
        } else {
            gemm_wmma<<<gemm_blocks, 256>>>(192, boff, b[l], 0, 1, -1, out);
        }
        int t = hin; hin = hout; hout = t;
    }
}

// round 14
// speedup vs baseline: 1.4141x; 1.4141x over previous
#include <cuda_runtime.h>
#include <cuda_bf16.h>
#include <mma.h>
#include <math.h>
#include <stdint.h>

using namespace nvcuda;

#define N_NODES 50000
#define N_EDGES 800000
#define IN_DIM  128
#define FEAT    64
#define SCAN_BLOCKS 196             // ceil(50001/256)
#define NXW 3200000                 // N_NODES*64 float2-units of x
#define WELEMS 45056                // pre_w(8192) + 3x w(12288)
#define COUNT_BLOCKS 3125
#define PREP_BLOCKS ((NXW + WELEMS + 255) / 256)

// ---------------- scratch (static device globals; no allocation) ----------------
__device__ float    g_H0[N_NODES * FEAT];
__device__ float    g_H1[N_NODES * FEAT];
__device__ unsigned g_Ahi[N_NODES * 96];     // split-bf16 A, packed bf16x2
__device__ unsigned g_Alo[N_NODES * 96];
__device__ __nv_bfloat16 g_Bhi[WELEMS];      // weights row-major [K,64], split-bf16
__device__ __nv_bfloat16 g_Blo[WELEMS];
__device__ int      g_cnt[N_NODES];
__device__ int      g_off[N_NODES + 1];
__device__ int      g_pos[N_NODES];
__device__ float4   g_ecsr[N_EDGES];         // packed (src_bits, ea0, ea1, ea2) in CSR order
__device__ int      g_bsum[256];

__device__ __forceinline__ float* sel_buf(int s) { return (s == 0) ? g_H0 : g_H1; }

__device__ __forceinline__ unsigned pack_bf2(__nv_bfloat16 a, __nv_bfloat16 b) {
    return ((unsigned)__bfloat16_as_ushort(b) << 16) | (unsigned)__bfloat16_as_ushort(a);
}
__device__ __forceinline__ void split2(float x, float y, unsigned& hi, unsigned& lo) {
    __nv_bfloat16 hx = __float2bfloat16(x), hy = __float2bfloat16(y);
    __nv_bfloat16 lx = __float2bfloat16(x - __bfloat162float(hx));
    __nv_bfloat16 ly = __float2bfloat16(y - __bfloat162float(hy));
    hi = pack_bf2(hx, hy);
    lo = pack_bf2(lx, ly);
}

// ---------------- zero cnt ----------------
__global__ void zero_cnt_kernel() {
    int i = blockIdx.x * blockDim.x + threadIdx.x;
    if (i < N_NODES) g_cnt[i] = 0;
}

// ---------------- K1: count in-degrees | prep (x + weights -> split bf16) ----------
__global__ void __launch_bounds__(256)
k_count_prep(const int* __restrict__ ei, const float* __restrict__ x,
             const float* __restrict__ pre_w, const float* __restrict__ w1,
             const float* __restrict__ w2, const float* __restrict__ w3)
{
    int b = blockIdx.x;
    if (b < COUNT_BLOCKS) {
        int e = b * 256 + threadIdx.x;
        if (e < N_EDGES) atomicAdd(&g_cnt[ei[N_EDGES + e]], 1);
    } else {
        int idx = (b - COUNT_BLOCKS) * 256 + threadIdx.x;
        if (idx < NXW) {
            float2 v = ((const float2*)x)[idx];
            unsigned hi, lo;
            split2(v.x, v.y, hi, lo);
            g_Ahi[idx] = hi;
            g_Alo[idx] = lo;
        } else {
            int j = idx - NXW;
            if (j < WELEMS) {
                const float* W; int off;
                if (j < 8192)       { W = pre_w; off = 0;     }
                else if (j < 20480) { W = w1;    off = 8192;  j -= 8192;  }
                else if (j < 32768) { W = w2;    off = 20480; j -= 20480; }
                else                { W = w3;    off = 32768; j -= 32768; }
                float wv = W[j];
                __nv_bfloat16 hi = __float2bfloat16(wv);
                g_Bhi[off + j] = hi;
                g_Blo[off + j] = __float2bfloat16(wv - __bfloat162float(hi));
            }
        }
    }
}

// ---------------- scan (two dedicated small launches, R12 structure) -------------
__global__ void scan1_kernel() {
    __shared__ int s[256];
    int t = threadIdx.x, i = blockIdx.x * 256 + t;
    int v = (i < N_NODES) ? g_cnt[i] : 0;
    s[t] = v; __syncthreads();
    #pragma unroll
    for (int d = 1; d < 256; d <<= 1) {
        int x = (t >= d) ? s[t - d] : 0;
        __syncthreads(); s[t] += x; __syncthreads();
    }
    if (i < N_NODES) g_off[i] = s[t] - v;
    if (t == 255) g_bsum[blockIdx.x] = s[255];
}
__global__ void scan23_kernel() {
    __shared__ int s[256];
    int t = threadIdx.x;
    s[t] = (t < SCAN_BLOCKS) ? g_bsum[t] : 0;
    __syncthreads();
    #pragma unroll
    for (int d = 1; d < 256; d <<= 1) {
        int x = (t >= d) ? s[t - d] : 0;
        __syncthreads(); s[t] += x; __syncthreads();
    }
    int blk = blockIdx.x;
    int add = (blk == 0) ? 0 : s[blk - 1];
    int i = blk * 256 + t;
    if (i < N_NODES) { int o = g_off[i] + add; g_off[i] = o; g_pos[i] = o; }
    if (i == N_NODES) g_off[N_NODES] = N_EDGES;
}

// ---------------- fill: packed CSR records ----------------
__global__ void fill_csr_kernel(const int* __restrict__ ei, const float* __restrict__ ea) {
    int e = blockIdx.x * blockDim.x + threadIdx.x;
    if (e < N_EDGES) {
        int t  = ei[N_EDGES + e];
        int s  = ei[e];
        float a0 = __ldg(&ea[(size_t)e * 3 + 0]);
        float a1 = __ldg(&ea[(size_t)e * 3 + 1]);
        float a2 = __ldg(&ea[(size_t)e * 3 + 2]);
        int slot = atomicAdd(&g_pos[t], 1);
        g_ecsr[slot] = make_float4(__int_as_float(s), a0, a1, a2);
    }
}

// ---------------- edge aggregation (packed metadata, R12 loop structure) ----------
__global__ void __launch_bounds__(256)
agg_kernel(int hsel)
{
    __shared__ float4 sE[8][32];
    int w = threadIdx.x >> 5;
    int node = blockIdx.x * 8 + w;
    if (node >= N_NODES) return;
    int lane = threadIdx.x & 31;
    const float* H = sel_buf(hsel);
    int off = g_off[node];
    int deg = g_off[node + 1] - off;

    float s0x = 0.f, s0y = 0.f, s1x = 0.f, s1y = 0.f, s2x = 0.f, s2y = 0.f;

    for (int base = 0; base < deg; base += 32) {
        if (base + lane < deg) sE[w][lane] = __ldg(&g_ecsr[off + base + lane]);
        __syncwarp();
        int m = min(32, deg - base);
        for (int k = 0; k < m; k++) {
            float4 ed = sE[w][k];                       // broadcast LDS.128
            int src = __float_as_int(ed.x);
            float2 hv = __ldg(&((const float2*)(H + (size_t)src * 64))[lane]);
            s0x += ed.y * hv.x; s0y += ed.y * hv.y;
            s1x += ed.z * hv.x; s1y += ed.z * hv.y;
            s2x += ed.w * hv.x; s2y += ed.w * hv.y;
        }
        __syncwarp();
    }

    float inv = 1.0f / fmaxf((float)deg, 1.0f);
    size_t rb = (size_t)node * 96;
    unsigned hi, lo;
    split2(s0x * inv, s0y * inv, hi, lo); g_Ahi[rb + lane]      = hi; g_Alo[rb + lane]      = lo;
    split2(s1x * inv, s1y * inv, hi, lo); g_Ahi[rb + 32 + lane] = hi; g_Alo[rb + 32 + lane] = lo;
    split2(s2x * inv, s2y * inv, hi, lo); g_Ahi[rb + 64 + lane] = hi; g_Alo[rb + 64 + lane] = lo;
}

// ---------------- WMMA bf16 split GEMM (pipelined), fused epilogue ----------------
#define GA_ST 40
#define GB_ST 72
__global__ void __launch_bounds__(256)
gemm_wmma(int K, int boff, const float* __restrict__ bias,
          int do_relu, int do_norm, int csel, float* __restrict__ extout)
{
    __shared__ __align__(16) unsigned char smemraw[33 * 1024];
    __nv_bfloat16* sAh = (__nv_bfloat16*)smemraw;
    __nv_bfloat16* sAl = sAh + 128 * GA_ST;
    __nv_bfloat16* sBh = sAl + 128 * GA_ST;
    __nv_bfloat16* sBl = sBh + 32 * GB_ST;
    float* sOut = (float*)smemraw;

    const int tid = threadIdx.x;
    const int wid = tid >> 5;
    const int lane = tid & 31;
    const int row0cta = blockIdx.x * 128;
    const int chunks = K >> 5;

    const __nv_bfloat16* Ah = (const __nv_bfloat16*)g_Ahi;
    const __nv_bfloat16* Al = (const __nv_bfloat16*)g_Alo;
    const __nv_bfloat16* Bh = g_Bhi + boff;
    const __nv_bfloat16* Bl = g_Blo + boff;

    const int ar0 = tid >> 2, aq = tid & 3;
    const int ar1 = 64 + ar0;
    const int brow = tid >> 3, bq = tid & 7;
    const int ga0 = row0cta + ar0, ga1 = row0cta + ar1;

    wmma::fragment<wmma::accumulator, 16, 16, 16, float> acc[4];
    #pragma unroll
    for (int j = 0; j < 4; j++) wmma::fill_fragment(acc[j], 0.0f);

    uint4 rah0, rah1, ral0, ral1, rbh, rbl;
    const uint4 z4 = make_uint4(0, 0, 0, 0);

    rah0 = (ga0 < N_NODES) ? ((const uint4*)(Ah + (size_t)ga0 * K))[aq] : z4;
    rah1 = (ga1 < N_NODES) ? ((const uint4*)(Ah + (size_t)ga1 * K))[aq] : z4;
    ral0 = (ga0 < N_NODES) ? ((const uint4*)(Al + (size_t)ga0 * K))[aq] : z4;
    ral1 = (ga1 < N_NODES) ? ((const uint4*)(Al + (size_t)ga1 * K))[aq] : z4;
    rbh  = ((const uint4*)(Bh + (size_t)brow * 64))[bq];
    rbl  = ((const uint4*)(Bl + (size_t)brow * 64))[bq];

    for (int c = 0; c < chunks; c++) {
        __syncthreads();
        ((uint4*)sAh)[ar0 * 5 + aq] = rah0;
        ((uint4*)sAh)[ar1 * 5 + aq] = rah1;
        ((uint4*)sAl)[ar0 * 5 + aq] = ral0;
        ((uint4*)sAl)[ar1 * 5 + aq] = ral1;
        ((uint4*)sBh)[brow * 9 + bq] = rbh;
        ((uint4*)sBl)[brow * 9 + bq] = rbl;
        if (c + 1 < chunks) {
            int k0 = (c + 1) << 5;
            rah0 = (ga0 < N_NODES) ? ((const uint4*)(Ah + (size_t)ga0 * K + k0))[aq] : z4;
            rah1 = (ga1 < N_NODES) ? ((const uint4*)(Ah + (size_t)ga1 * K + k0))[aq] : z4;
            ral0 = (ga0 < N_NODES) ? ((const uint4*)(Al + (size_t)ga0 * K + k0))[aq] : z4;
            ral1 = (ga1 < N_NODES) ? ((const uint4*)(Al + (size_t)ga1 * K + k0))[aq] : z4;
            rbh  = ((const uint4*)(Bh + (size_t)(k0 + brow) * 64))[bq];
            rbl  = ((const uint4*)(Bl + (size_t)(k0 + brow) * 64))[bq];
        }
        __syncthreads();
        #pragma unroll
        for (int ks = 0; ks < 2; ks++) {
            wmma::fragment<wmma::matrix_a, 16, 16, 16, __nv_bfloat16, wmma::row_major> ah, al;
            wmma::load_matrix_sync(ah, sAh + wid * 16 * GA_ST + ks * 16, GA_ST);
            wmma::load_matrix_sync(al, sAl + wid * 16 * GA_ST + ks * 16, GA_ST);
            #pragma unroll
            for (int j = 0; j < 4; j++) {
                wmma::fragment<wmma::matrix_b, 16, 16, 16, __nv_bfloat16, wmma::row_major> bh, bl;
                wmma::load_matrix_sync(bh, sBh + ks * 16 * GB_ST + j * 16, GB_ST);
                wmma::load_matrix_sync(bl, sBl + ks * 16 * GB_ST + j * 16, GB_ST);
                wmma::mma_sync(acc[j], ah, bh, acc[j]);
                wmma::mma_sync(acc[j], al, bh, acc[j]);
                wmma::mma_sync(acc[j], ah, bl, acc[j]);
            }
        }
    }

    __syncthreads();
    #pragma unroll
    for (int j = 0; j < 4; j++)
        wmma::store_matrix_sync(&sOut[wid * 1024 + j * 16], acc[j], 64, wmma::mem_row_major);
    __syncwarp();

    int r = lane & 15, half = lane >> 4;
    int row = row0cta + wid * 16 + r;
    const float* src = &sOut[wid * 1024 + r * 64 + half * 32];
    float v[32];
    float ss = 0.0f;
    #pragma unroll
    for (int j = 0; j < 32; j++) {
        v[j] = src[j] + __ldg(&bias[half * 32 + j]);
        if (do_relu) v[j] = fmaxf(v[j], 0.0f);
        ss += v[j] * v[j];
    }
    if (do_norm) {
        ss += __shfl_xor_sync(0xffffffffu, ss, 16);
        float rr = 1.0f / fmaxf(sqrtf(ss), 1e-12f);
        #pragma unroll
        for (int j = 0; j < 32; j++) v[j] *= rr;
    }
    if (row < N_NODES) {
        float* C = (csel < 0) ? extout : sel_buf(csel);
        float4* po = (float4*)(C + (size_t)row * 64 + half * 32);
        #pragma unroll
        for (int j = 0; j < 8; j++)
            po[j] = make_float4(v[4 * j], v[4 * j + 1], v[4 * j + 2], v[4 * j + 3]);
    }
}

// ---------------- launch (kernel launches ONLY — graph-capture safe) ----------------
extern "C" void kernel_launch(void* const* d_in, const int* in_sizes, int n_in,
                              void* d_out, int out_size)
{
    const float* x     = (const float*)d_in[0];
    const int*   ei    = (const int*)  d_in[1];   // [2, E]
    const float* ea    = (const float*)d_in[2];   // [E, 3]
    const float* pre_w = (const float*)d_in[3];   // [128, 64]
    const float* pre_b = (const float*)d_in[4];   // [64]
    const float* w[3]  = {(const float*)d_in[5], (const float*)d_in[7], (const float*)d_in[9]};
    const float* b[3]  = {(const float*)d_in[6], (const float*)d_in[8], (const float*)d_in[10]};
    float* out = (float*)d_out;

    const int gemm_blocks = (N_NODES + 127) / 128;   // 391

    // ---- CSR build + dtype prep ----
    zero_cnt_kernel<<<(N_NODES + 255) / 256, 256>>>();
    k_count_prep<<<COUNT_BLOCKS + PREP_BLOCKS, 256>>>(ei, x, pre_w, w[0], w[1], w[2]);
    scan1_kernel<<<SCAN_BLOCKS, 256>>>();
    scan23_kernel<<<SCAN_BLOCKS + 1, 256>>>();
    fill_csr_kernel<<<(N_EDGES + 255) / 256, 256>>>(ei, ea);

    // ---- linear_pre: H0 = x @ pre_w + pre_b (K=128, B offset 0) ----
    gemm_wmma<<<gemm_blocks, 256>>>(IN_DIM, 0, pre_b, 0, 0, 0, nullptr);

    int hin = 0, hout = 1;
    for (int l = 0; l < 3; l++) {
        agg_kernel<<<(N_NODES + 7) / 8, 256>>>(hin);      // -> split-bf16 A (K=192)
        int boff = 8192 + l * 12288;
        if (l < 2) {
            gemm_wmma<<<gemm_blocks, 256>>>(192, boff, b[l], 1, 0, hout, nullptr);
        } else {
            gemm_wmma<<<gemm_blocks, 256>>>(192, boff, b[l], 0, 1, -1, out);
        }
        int t = hin; hin = hout; hout = t;
    }
}